// round 6
// baseline (speedup 1.0000x reference)
#include <cuda_runtime.h>
#include <cuda_bf16.h>

// Problem constants (fixed by the dataset)
#define BATCH 8
#define CH    256
#define NPTS  65536
#define HID   256
#define OUTC  8
#define TOPK  512

// Scratch (no cudaMalloc allowed). All zero-init at load; every kernel that
// consumes a scratch buffer resets it for the next graph replay.
__device__ float g_score[BATCH * NPTS];
__device__ int   g_topk_idx[BATCH * TOPK];
__device__ unsigned int g_hist16[BATCH * 65536];          // 2 MB
__device__ unsigned long long g_cand[BATCH * 8192];        // 512 KB
__device__ int g_cnt[BATCH];
__device__ int g_thresh[BATCH];

#define CAP 8192

// ---------------- packed f32x2 helpers ----------------
__device__ __forceinline__ unsigned long long pack2(float lo, float hi) {
    unsigned long long r;
    asm("mov.b64 %0, {%1, %2};" : "=l"(r) : "f"(lo), "f"(hi));
    return r;
}
__device__ __forceinline__ void unpack2(unsigned long long v, float& lo, float& hi) {
    asm("mov.b64 {%0, %1}, %2;" : "=f"(lo), "=f"(hi) : "l"(v));
}
__device__ __forceinline__ void fma2(unsigned long long& d, unsigned long long a, unsigned long long b) {
    asm("fma.rn.f32x2 %0, %1, %2, %0;" : "+l"(d) : "l"(a), "l"(b));
}

// ---------------- cp.async helpers ----------------
__device__ __forceinline__ void cp16(void* dst_smem, const void* src) {
    unsigned s = (unsigned)__cvta_generic_to_shared(dst_smem);
    asm volatile("cp.async.cg.shared.global [%0], [%1], 16;" :: "r"(s), "l"(src));
}
__device__ __forceinline__ void cp_commit() {
    asm volatile("cp.async.commit_group;");
}
__device__ __forceinline__ void cp_wait0() {
    asm volatile("cp.async.wait_group 0;");
}

// ---------------- Phase A: score GEMM ----------------
// FC1: strictly sequential ascending-k FMA chain per output.
// FC2 (score): 4 slices, slice z owns k in {16*i + 4z .. 16*i + 4z + 3},
// each slice a sequential ascending chain, combined ((s0+s1)+s2)+s3.
// (This exact order passed with rel_err 2e-7 — do not change.)
#define PTS 64
#define KT  16
#define NK  (CH / KT)   // 16 k-tiles

#define DYN_FLOATS 16384   // staging (10240 f) aliased with hmat (16384 f)

__global__ void __launch_bounds__(256, 2)
score_kernel(const float* __restrict__ feat, const float* __restrict__ W1,
             const float* __restrict__ b1, const float* __restrict__ W2,
             const float* __restrict__ b2) {
    extern __shared__ float dyn[];
    float* w1s = dyn;            // [2][KT*256]
    float* fs  = dyn + 8192;     // [2][KT*PTS]
    float* hmat = dyn;           // aliases staging after the loop
    __shared__ float w2s[256];   // W2[:,7]
    __shared__ float ps[256];    // FC2 slice partials

    const int tid = threadIdx.x;
    const int b = blockIdx.y;
    const int n0 = blockIdx.x * PTS;
    const int row = tid >> 4;   // hid group: hid in [row*16, row*16+16)
    const int col = tid & 15;   // pt group:  pt  in [col*4, col*4+4)

    w2s[tid] = W2[tid * OUTC + 7];

    const float* fbase = feat + (size_t)b * CH * NPTS + n0;

    const int wkk[4] = { (tid + 0) >> 6, (tid + 256) >> 6, (tid + 512) >> 6, (tid + 768) >> 6 };
    const int wc4 = (tid & 63) << 2;
    const int fkk_ = tid >> 4;
    const int fp4 = (tid & 15) << 2;

    auto issue = [&](int t, int buf) {
        const int k0 = t * KT;
        float* wdst = w1s + buf * (KT * 256);
        float* fdst = fs + buf * (KT * PTS);
#pragma unroll
        for (int j = 0; j < 4; j++)
            cp16(&wdst[wkk[j] * 256 + wc4],
                 &W1[(size_t)(k0 + wkk[j]) * HID + wc4]);
        cp16(&fdst[fkk_ * PTS + fp4],
             &fbase[(size_t)(k0 + fkk_) * NPTS + fp4]);
        cp_commit();
    };

    unsigned long long acc[8][4];
#pragma unroll
    for (int i = 0; i < 8; i++)
#pragma unroll
        for (int j = 0; j < 4; j++) acc[i][j] = 0ULL;

    issue(0, 0);

    int p = 0;
#pragma unroll 1
    for (int t = 0; t < NK; t++) {
        cp_wait0();
        __syncthreads();     // buf[p] staged by all; buf[p^1] fully consumed
        if (t + 1 < NK) issue(t + 1, p ^ 1);

        const float* wsrc = w1s + p * (KT * 256);
        const float* fsrc = fs + p * (KT * PTS);
#pragma unroll
        for (int kk = 0; kk < KT; kk++) {
            unsigned long long wp[8];
#pragma unroll
            for (int i = 0; i < 4; i++) {
                ulonglong2 v = *(const ulonglong2*)&wsrc[kk * 256 + row * 16 + i * 4];
                wp[2 * i] = v.x;
                wp[2 * i + 1] = v.y;
            }
            float4 fq = *(const float4*)&fsrc[kk * PTS + col * 4];
            unsigned long long fv[4];
            fv[0] = pack2(fq.x, fq.x);
            fv[1] = pack2(fq.y, fq.y);
            fv[2] = pack2(fq.z, fq.z);
            fv[3] = pack2(fq.w, fq.w);
#pragma unroll
            for (int hp = 0; hp < 8; hp++)
#pragma unroll
                for (int tp = 0; tp < 4; tp++)
                    fma2(acc[hp][tp], wp[hp], fv[tp]);
        }
        p ^= 1;
    }
    __syncthreads();   // staging reads done before hmat overwrites it

    // bias + relu -> hmat[hid][pt]
#pragma unroll
    for (int hp = 0; hp < 8; hp++) {
        int h0 = row * 16 + hp * 2;
        float b1a = b1[h0], b1b = b1[h0 + 1];
#pragma unroll
        for (int tp = 0; tp < 4; tp++) {
            float lo, hi;
            unpack2(acc[hp][tp], lo, hi);
            int pt = col * 4 + tp;
            hmat[h0 * PTS + pt] = fmaxf(lo + b1a, 0.0f);
            hmat[(h0 + 1) * PTS + pt] = fmaxf(hi + b1b, 0.0f);
        }
    }
    __syncthreads();

    // FC2 score: slice-parallel, 4 threads per point.
    {
        const int z = tid >> 6;
        const int pt = tid & 63;
        float a = 0.0f;
#pragma unroll
        for (int i = 0; i < 16; i++) {
            int base = 16 * i + 4 * z;
#pragma unroll
            for (int kk = 0; kk < 4; kk++)
                a = fmaf(hmat[(base + kk) * PTS + pt], w2s[base + kk], a);
        }
        ps[tid] = a;
    }
    __syncthreads();

    if (tid < PTS) {
        float sc = ((ps[tid] + ps[64 + tid]) + ps[128 + tid]) + ps[192 + tid];
        g_score[(size_t)b * NPTS + n0 + tid] = sc + b2[7];
    }
}

// ---------------- Phase B: exact top-512 per batch ----------------
__device__ __forceinline__ unsigned int fkey(float f) {
    unsigned int u = __float_as_uint(f);
    return (u & 0x80000000u) ? ~u : (u | 0x80000000u);
}

// B1: 16-bit histogram. grid (BATCH, 8), 1024 threads, global atomics.
__global__ void hist16_kernel() {
    const int b = blockIdx.x;
    const float* sc = g_score + (size_t)b * NPTS;
    const int base = blockIdx.y * (NPTS / 8);
    unsigned int* h = g_hist16 + (size_t)b * 65536;
    for (int i = threadIdx.x; i < NPTS / 8; i += 1024)
        atomicAdd(&h[fkey(sc[base + i]) >> 16], 1u);
}

// B2: per-batch exact 16-bit threshold via block suffix-scan over 65536 bins.
// Finds max v16 with count(key16 >= v16) >= TOPK; resets bins afterwards.
__global__ void thresh_kernel() {
    __shared__ unsigned int sfx[1024];
    const int b = blockIdx.x;
    const int tid = threadIdx.x;
    unsigned int* h = g_hist16 + (size_t)b * 65536;
    const int c0 = tid * 64;

    unsigned int s = 0;
#pragma unroll 8
    for (int j = 0; j < 64; j++) s += h[c0 + j];
    sfx[tid] = s;
    __syncthreads();

    // inclusive suffix scan (doubling)
    for (int off = 1; off < 1024; off <<= 1) {
        unsigned int v = sfx[tid];
        unsigned int add = (tid + off < 1024) ? sfx[tid + off] : 0u;
        __syncthreads();
        sfx[tid] = v + add;
        __syncthreads();
    }

    unsigned int above = (tid < 1023) ? sfx[tid + 1] : 0u;
    if (sfx[tid] >= TOPK && above < TOPK) {
        // crossing is inside this thread's chunk: walk bins from the top
        unsigned int cum = above;
        for (int v = c0 + 63; v >= c0; v--) {
            cum += h[v];
            if (cum >= TOPK) { g_thresh[b] = v; break; }
        }
    }
    __syncthreads();
    // self-reset for next replay
#pragma unroll 8
    for (int j = 0; j < 64; j++) h[c0 + j] = 0u;
}

// B3: parallel candidate collect. grid (BATCH, 8).
__global__ void collect_kernel() {
    const int b = blockIdx.x;
    const unsigned int v16 = (unsigned int)g_thresh[b];
    const float* sc = g_score + (size_t)b * NPTS;
    const int base = blockIdx.y * (NPTS / 8);
    for (int i = threadIdx.x; i < NPTS / 8; i += 1024) {
        int gi = base + i;
        unsigned int u = fkey(sc[gi]);
        if ((u >> 16) >= v16) {
            int p = atomicAdd(&g_cnt[b], 1);
            if (p < CAP)
                g_cand[(size_t)b * CAP + p] =
                    ((unsigned long long)u << 32) |
                    (unsigned long long)(0xFFFFFFFFu - (unsigned int)gi);
        }
    }
}

// B4: per-batch sort of candidates (exact composite key), emit top 512, reset.
__global__ void sort_kernel() {
    extern __shared__ unsigned long long cand[];   // CAP entries
    __shared__ int s_m;
    const int b = blockIdx.x;
    const int tid = threadIdx.x;

    const int M0 = g_cnt[b];
    const int M = M0 < CAP ? M0 : CAP;
    if (tid == 0) {
        int m = 1024;
        while (m < M) m <<= 1;
        s_m = m;
    }
    __syncthreads();
    const int m = s_m;

    for (int i = tid; i < m; i += 1024)
        cand[i] = (i < M) ? g_cand[(size_t)b * CAP + i] : 0ULL;
    __syncthreads();

    for (unsigned int k = 2; k <= (unsigned int)m; k <<= 1) {
        for (unsigned int j = k >> 1; j > 0; j >>= 1) {
            for (unsigned int i = tid; i < (unsigned int)m; i += 1024) {
                unsigned int ixj = i ^ j;
                if (ixj > i) {
                    unsigned long long a = cand[i], c2 = cand[ixj];
                    bool up = ((i & k) == 0);
                    if ((a > c2) == up) { cand[i] = c2; cand[ixj] = a; }
                }
            }
            __syncthreads();
        }
    }
    if (tid < TOPK) {
        unsigned long long e = cand[m - 1 - tid];
        g_topk_idx[b * TOPK + tid] =
            (int)(0xFFFFFFFFu - (unsigned int)(e & 0xFFFFFFFFULL));
    }
    if (tid == 0) g_cnt[b] = 0;   // self-reset for next replay
}

// ---------------- Phase C: recompute full 8-channel MLP at selected points ----------------
#define GP 16
__global__ void __launch_bounds__(256)
gather_kernel(const float* __restrict__ feat, const float* __restrict__ W1,
              const float* __restrict__ b1, const float* __restrict__ W2,
              const float* __restrict__ b2, float* __restrict__ out) {
    __shared__ float fcol[CH][GP];
    __shared__ float hs[HID][GP];
    __shared__ float w2s[HID * OUTC];
    __shared__ int nidx[GP];

    const int tid = threadIdx.x;
    const int b = blockIdx.x >> 5;            // 32 blocks per batch
    const int r0 = (blockIdx.x & 31) * GP;

    if (tid < GP) nidx[tid] = g_topk_idx[b * TOPK + r0 + tid];
    for (int i = tid; i < HID * OUTC; i += 256) w2s[i] = W2[i];
    __syncthreads();

#pragma unroll
    for (int p = 0; p < GP; p++)
        fcol[tid][p] = feat[((size_t)b * CH + tid) * NPTS + nidx[p]];
    __syncthreads();

    float acc[GP];
#pragma unroll
    for (int p = 0; p < GP; p++) acc[p] = 0.0f;
#pragma unroll 4
    for (int c = 0; c < CH; c++) {
        float w = W1[(size_t)c * HID + tid];
#pragma unroll
        for (int p = 0; p < GP; p++) acc[p] = fmaf(fcol[c][p], w, acc[p]);
    }
    float b1v = b1[tid];
#pragma unroll
    for (int p = 0; p < GP; p++) hs[tid][p] = fmaxf(acc[p] + b1v, 0.0f);
    __syncthreads();

    if (tid < GP * OUTC) {
        int p = tid >> 3, o = tid & 7;
        float a = 0.0f;
#pragma unroll 16
        for (int hh = 0; hh < HID; hh++)
            a = fmaf(hs[hh][p], w2s[hh * OUTC + o], a);
        out[((size_t)(b * TOPK + r0 + p)) * OUTC + o] = a + b2[o];
    }
}

// ---------------- launch ----------------
extern "C" void kernel_launch(void* const* d_in, const int* in_sizes, int n_in,
                              void* d_out, int out_size) {
    // inputs: 0 points(unused), 1 features, 2 W1, 3 b1, 4 W2, 5 b2, 6 topk
    const float* feat = (const float*)d_in[1];
    const float* W1 = (const float*)d_in[2];
    const float* b1 = (const float*)d_in[3];
    const float* W2 = (const float*)d_in[4];
    const float* b2 = (const float*)d_in[5];
    float* out = (float*)d_out;

    cudaFuncSetAttribute(score_kernel, cudaFuncAttributeMaxDynamicSharedMemorySize,
                         DYN_FLOATS * (int)sizeof(float));
    cudaFuncSetAttribute(sort_kernel, cudaFuncAttributeMaxDynamicSharedMemorySize,
                         CAP * (int)sizeof(unsigned long long));

    dim3 gA(NPTS / PTS, BATCH);
    score_kernel<<<gA, 256, DYN_FLOATS * sizeof(float)>>>(feat, W1, b1, W2, b2);
    hist16_kernel<<<dim3(BATCH, 8), 1024>>>();
    thresh_kernel<<<BATCH, 1024>>>();
    collect_kernel<<<dim3(BATCH, 8), 1024>>>();
    sort_kernel<<<BATCH, 1024, CAP * sizeof(unsigned long long)>>>();
    gather_kernel<<<BATCH * (TOPK / GP), 256>>>(feat, W1, b1, W2, b2, out);
}

// round 7
// speedup vs baseline: 1.6404x; 1.6404x over previous
#include <cuda_runtime.h>
#include <cuda_bf16.h>

// Problem constants (fixed by the dataset)
#define BATCH 8
#define CH    256
#define NPTS  65536
#define HID   256
#define OUTC  8
#define TOPK  512

// Scratch (no cudaMalloc allowed). Zero-init at load; every consumer resets
// its buffer for the next graph replay (replay-deterministic).
__device__ float g_score[BATCH * NPTS];
__device__ int   g_topk_idx[BATCH * TOPK];
__device__ unsigned int g_hist16[BATCH * 65536];          // reset by thresh_kernel
__device__ unsigned long long g_cand[BATCH * 8192];
__device__ int g_cnt[BATCH];                               // reset by sort_kernel
__device__ int g_thresh[BATCH];

#define CAP 8192

// ---------------- packed f32x2 helpers ----------------
__device__ __forceinline__ unsigned long long pack2(float lo, float hi) {
    unsigned long long r;
    asm("mov.b64 %0, {%1, %2};" : "=l"(r) : "f"(lo), "f"(hi));
    return r;
}
__device__ __forceinline__ void unpack2(unsigned long long v, float& lo, float& hi) {
    asm("mov.b64 {%0, %1}, %2;" : "=f"(lo), "=f"(hi) : "l"(v));
}
__device__ __forceinline__ void fma2(unsigned long long& d, unsigned long long a, unsigned long long b) {
    asm("fma.rn.f32x2 %0, %1, %2, %0;" : "+l"(d) : "l"(a), "l"(b));
}

// ---------------- cp.async helpers ----------------
__device__ __forceinline__ void cp16(void* dst_smem, const void* src) {
    unsigned s = (unsigned)__cvta_generic_to_shared(dst_smem);
    asm volatile("cp.async.cg.shared.global [%0], [%1], 16;" :: "r"(s), "l"(src));
}
__device__ __forceinline__ void cp_commit() {
    asm volatile("cp.async.commit_group;");
}
__device__ __forceinline__ void cp_wait1() {
    asm volatile("cp.async.wait_group 1;");
}
__device__ __forceinline__ void cp_wait0() {
    asm volatile("cp.async.wait_group 0;");
}

__device__ __forceinline__ unsigned int fkey(float f) {
    unsigned int u = __float_as_uint(f);
    return (u & 0x80000000u) ? ~u : (u | 0x80000000u);
}

// ---------------- Phase A: score GEMM (round-4 mainloop, verbatim) ----------------
// FC1: strictly sequential ascending-k FMA chain per output.
// FC2 (score): 4 slices, slice z owns k in {16*i + 4z .. 16*i + 4z + 3},
// each slice a sequential ascending chain, combined ((s0+s1)+s2)+s3.
// (This exact order passed with rel_err 2e-7 — do not change.)
#define PTS 64
#define KT  16
#define NK  (CH / KT)   // 16 k-tiles

__global__ void __launch_bounds__(256, 2)
score_kernel(const float* __restrict__ feat, const float* __restrict__ W1,
             const float* __restrict__ b1, const float* __restrict__ W2,
             const float* __restrict__ b2) {
    __shared__ float w1s[2][KT * 256];  // 2 x 16 KB
    __shared__ float fs[2][KT * PTS];   // 2 x 4 KB
    __shared__ float w2s[256];          // 1 KB : W2[:,7]
    extern __shared__ float hmat[];     // 256*64 floats = 64 KB (dynamic)

    const int tid = threadIdx.x;
    const int b = blockIdx.y;
    const int n0 = blockIdx.x * PTS;
    const int row = tid >> 4;   // hid group: hid in [row*16, row*16+16)
    const int col = tid & 15;   // pt group:  pt  in [col*4, col*4+4)

    w2s[tid] = W2[tid * OUTC + 7];

    const float* fbase = feat + (size_t)b * CH * NPTS + n0;

    // staging coordinates (per thread): 4 float4 of W1, 1 float4 of f
    const int wkk[4] = { (tid + 0) >> 6, (tid + 256) >> 6, (tid + 512) >> 6, (tid + 768) >> 6 };
    const int wc4 = (tid & 63) << 2;
    const int fkk_ = tid >> 4;
    const int fp4 = (tid & 15) << 2;

    auto issue = [&](int t, int buf) {
        const int k0 = t * KT;
#pragma unroll
        for (int j = 0; j < 4; j++)
            cp16(&w1s[buf][wkk[j] * 256 + wc4],
                 &W1[(size_t)(k0 + wkk[j]) * HID + wc4]);
        cp16(&fs[buf][fkk_ * PTS + fp4],
             &fbase[(size_t)(k0 + fkk_) * NPTS + fp4]);
        cp_commit();
    };

    unsigned long long acc[8][4];
#pragma unroll
    for (int i = 0; i < 8; i++)
#pragma unroll
        for (int j = 0; j < 4; j++) acc[i][j] = 0ULL;

    // depth-2 pipeline prologue
    issue(0, 0);
    issue(1, 1);

    int p = 0;
#pragma unroll 1
    for (int t = 0; t < NK; t++) {
        if (t + 1 < NK) cp_wait1(); else cp_wait0();
        __syncthreads();   // buf[p] fully staged across all threads

#pragma unroll
        for (int kk = 0; kk < KT; kk++) {
            unsigned long long wp[8];
#pragma unroll
            for (int i = 0; i < 4; i++) {
                ulonglong2 v = *(const ulonglong2*)&w1s[p][kk * 256 + row * 16 + i * 4];
                wp[2 * i] = v.x;
                wp[2 * i + 1] = v.y;
            }
            float4 fq = *(const float4*)&fs[p][kk * PTS + col * 4];
            unsigned long long fv[4];
            fv[0] = pack2(fq.x, fq.x);
            fv[1] = pack2(fq.y, fq.y);
            fv[2] = pack2(fq.z, fq.z);
            fv[3] = pack2(fq.w, fq.w);
#pragma unroll
            for (int hp = 0; hp < 8; hp++)
#pragma unroll
                for (int tp = 0; tp < 4; tp++)
                    fma2(acc[hp][tp], wp[hp], fv[tp]);
        }

        __syncthreads();   // all threads done reading buf[p] before reuse
        if (t + 2 < NK) issue(t + 2, p);
        p ^= 1;
    }

    // bias + relu -> hmat[hid][pt]
#pragma unroll
    for (int hp = 0; hp < 8; hp++) {
        int h0 = row * 16 + hp * 2;
        float b1a = b1[h0], b1b = b1[h0 + 1];
#pragma unroll
        for (int tp = 0; tp < 4; tp++) {
            float lo, hi;
            unpack2(acc[hp][tp], lo, hi);
            int pt = col * 4 + tp;
            hmat[(size_t)h0 * PTS + pt] = fmaxf(lo + b1a, 0.0f);
            hmat[(size_t)(h0 + 1) * PTS + pt] = fmaxf(hi + b1b, 0.0f);
        }
    }
    __syncthreads();

    // FC2 score: slice-parallel, 4 threads per point (z = tid>>6, pt = tid&63).
    float* ps = &w1s[0][0];   // reuse staging smem for partials: ps[z*64+pt]
    {
        const int z = tid >> 6;
        const int pt = tid & 63;
        float a = 0.0f;
#pragma unroll
        for (int i = 0; i < 16; i++) {
            int base = 16 * i + 4 * z;
#pragma unroll
            for (int kk = 0; kk < 4; kk++)
                a = fmaf(hmat[(base + kk) * PTS + pt], w2s[base + kk], a);
        }
        ps[tid] = a;
    }
    __syncthreads();

    if (tid < PTS) {
        float sc = ((ps[tid] + ps[64 + tid]) + ps[128 + tid]) + ps[192 + tid];
        sc += b2[7];
        g_score[(size_t)b * NPTS + n0 + tid] = sc;
        // fused 16-bit histogram (replaces the standalone hist kernel)
        atomicAdd(&g_hist16[(size_t)b * 65536 + (fkey(sc) >> 16)], 1u);
    }
}

// ---------------- Phase B: exact top-512 per batch ----------------

// B2: per-batch exact 16-bit threshold via block suffix-scan over 65536 bins.
// Finds max v16 with count(key16 >= v16) >= TOPK; resets bins afterwards.
__global__ void thresh_kernel() {
    __shared__ unsigned int sfx[1024];
    const int b = blockIdx.x;
    const int tid = threadIdx.x;
    unsigned int* h = g_hist16 + (size_t)b * 65536;
    const int c0 = tid * 64;

    unsigned int s = 0;
#pragma unroll 8
    for (int j = 0; j < 64; j++) s += h[c0 + j];
    sfx[tid] = s;
    __syncthreads();

    // inclusive suffix scan (doubling)
    for (int off = 1; off < 1024; off <<= 1) {
        unsigned int v = sfx[tid];
        unsigned int add = (tid + off < 1024) ? sfx[tid + off] : 0u;
        __syncthreads();
        sfx[tid] = v + add;
        __syncthreads();
    }

    unsigned int above = (tid < 1023) ? sfx[tid + 1] : 0u;
    if (sfx[tid] >= TOPK && above < TOPK) {
        unsigned int cum = above;
        for (int v = c0 + 63; v >= c0; v--) {
            cum += h[v];
            if (cum >= TOPK) { g_thresh[b] = v; break; }
        }
    }
    __syncthreads();
    // self-reset for next replay
#pragma unroll 8
    for (int j = 0; j < 64; j++) h[c0 + j] = 0u;
}

// B3: parallel candidate collect. grid (BATCH, 8).
__global__ void collect_kernel() {
    const int b = blockIdx.x;
    const unsigned int v16 = (unsigned int)g_thresh[b];
    const float* sc = g_score + (size_t)b * NPTS;
    const int base = blockIdx.y * (NPTS / 8);
    for (int i = threadIdx.x; i < NPTS / 8; i += 1024) {
        int gi = base + i;
        unsigned int u = fkey(sc[gi]);
        if ((u >> 16) >= v16) {
            int p = atomicAdd(&g_cnt[b], 1);
            if (p < CAP)
                g_cand[(size_t)b * CAP + p] =
                    ((unsigned long long)u << 32) |
                    (unsigned long long)(0xFFFFFFFFu - (unsigned int)gi);
        }
    }
}

// B4: per-batch sort of candidates (exact composite key), emit top 512, reset.
__global__ void sort_kernel() {
    extern __shared__ unsigned long long cand[];   // CAP entries
    __shared__ int s_m;
    const int b = blockIdx.x;
    const int tid = threadIdx.x;

    const int M0 = g_cnt[b];
    const int M = M0 < CAP ? M0 : CAP;
    if (tid == 0) {
        int m = 1024;
        while (m < M) m <<= 1;
        s_m = m;
    }
    __syncthreads();
    const int m = s_m;

    for (int i = tid; i < m; i += 1024)
        cand[i] = (i < M) ? g_cand[(size_t)b * CAP + i] : 0ULL;
    __syncthreads();

    for (unsigned int k = 2; k <= (unsigned int)m; k <<= 1) {
        for (unsigned int j = k >> 1; j > 0; j >>= 1) {
            for (unsigned int i = tid; i < (unsigned int)m; i += 1024) {
                unsigned int ixj = i ^ j;
                if (ixj > i) {
                    unsigned long long a = cand[i], c2 = cand[ixj];
                    bool up = ((i & k) == 0);
                    if ((a > c2) == up) { cand[i] = c2; cand[ixj] = a; }
                }
            }
            __syncthreads();
        }
    }
    if (tid < TOPK) {
        unsigned long long e = cand[m - 1 - tid];
        g_topk_idx[b * TOPK + tid] =
            (int)(0xFFFFFFFFu - (unsigned int)(e & 0xFFFFFFFFULL));
    }
    if (tid == 0) g_cnt[b] = 0;   // self-reset for next replay
}

// ---------------- Phase C: recompute full 8-channel MLP at selected points ----------------
#define GP 16
__global__ void __launch_bounds__(256)
gather_kernel(const float* __restrict__ feat, const float* __restrict__ W1,
              const float* __restrict__ b1, const float* __restrict__ W2,
              const float* __restrict__ b2, float* __restrict__ out) {
    __shared__ float fcol[CH][GP];
    __shared__ float hs[HID][GP];
    __shared__ float w2s[HID * OUTC];
    __shared__ int nidx[GP];

    const int tid = threadIdx.x;
    const int b = blockIdx.x >> 5;            // 32 blocks per batch
    const int r0 = (blockIdx.x & 31) * GP;

    if (tid < GP) nidx[tid] = g_topk_idx[b * TOPK + r0 + tid];
    for (int i = tid; i < HID * OUTC; i += 256) w2s[i] = W2[i];
    __syncthreads();

#pragma unroll
    for (int p = 0; p < GP; p++)
        fcol[tid][p] = feat[((size_t)b * CH + tid) * NPTS + nidx[p]];
    __syncthreads();

    float acc[GP];
#pragma unroll
    for (int p = 0; p < GP; p++) acc[p] = 0.0f;
#pragma unroll 4
    for (int c = 0; c < CH; c++) {
        float w = W1[(size_t)c * HID + tid];
#pragma unroll
        for (int p = 0; p < GP; p++) acc[p] = fmaf(fcol[c][p], w, acc[p]);
    }
    float b1v = b1[tid];
#pragma unroll
    for (int p = 0; p < GP; p++) hs[tid][p] = fmaxf(acc[p] + b1v, 0.0f);
    __syncthreads();

    if (tid < GP * OUTC) {
        int p = tid >> 3, o = tid & 7;
        float a = 0.0f;
#pragma unroll 16
        for (int hh = 0; hh < HID; hh++)
            a = fmaf(hs[hh][p], w2s[hh * OUTC + o], a);
        out[((size_t)(b * TOPK + r0 + p)) * OUTC + o] = a + b2[o];
    }
}

// ---------------- launch ----------------
extern "C" void kernel_launch(void* const* d_in, const int* in_sizes, int n_in,
                              void* d_out, int out_size) {
    // inputs: 0 points(unused), 1 features, 2 W1, 3 b1, 4 W2, 5 b2, 6 topk
    const float* feat = (const float*)d_in[1];
    const float* W1 = (const float*)d_in[2];
    const float* b1 = (const float*)d_in[3];
    const float* W2 = (const float*)d_in[4];
    const float* b2 = (const float*)d_in[5];
    float* out = (float*)d_out;

    cudaFuncSetAttribute(score_kernel, cudaFuncAttributeMaxDynamicSharedMemorySize,
                         256 * PTS * (int)sizeof(float));
    cudaFuncSetAttribute(sort_kernel, cudaFuncAttributeMaxDynamicSharedMemorySize,
                         CAP * (int)sizeof(unsigned long long));

    dim3 gA(NPTS / PTS, BATCH);
    score_kernel<<<gA, 256, 256 * PTS * sizeof(float)>>>(feat, W1, b1, W2, b2);
    thresh_kernel<<<BATCH, 1024>>>();
    collect_kernel<<<dim3(BATCH, 8), 1024>>>();
    sort_kernel<<<BATCH, 1024, CAP * sizeof(unsigned long long)>>>();
    gather_kernel<<<BATCH * (TOPK / GP), 256>>>(feat, W1, b1, W2, b2, out);
}

// round 8
// speedup vs baseline: 1.7642x; 1.0755x over previous
#include <cuda_runtime.h>
#include <cuda_bf16.h>

// Problem constants (fixed by the dataset)
#define BATCH 8
#define CH    256
#define NPTS  65536
#define HID   256
#define OUTC  8
#define TOPK  512

#define CAP   8192
#define BAND  64       // 16-bit buckets below approx threshold to keep

// Scratch (no cudaMalloc). Zero-init at load; consumers self-reset for replay.
__device__ float g_score[BATCH * NPTS];                    // approx scores
__device__ int   g_topk_idx[BATCH * TOPK];
__device__ unsigned int g_hist16[BATCH * 65536];           // reset by thresh_kernel
__device__ int g_candidx[BATCH * CAP];
__device__ unsigned long long g_cand[BATCH * CAP];
__device__ int g_cnt[BATCH];                               // reset by sort_kernel
__device__ int g_thresh[BATCH];

__device__ __forceinline__ unsigned int fkey(float f) {
    unsigned int u = __float_as_uint(f);
    return (u & 0x80000000u) ? ~u : (u | 0x80000000u);
}

// ================= Phase A: approximate scores via bf16 tensor cores =========
// Per block: 128 points, full K=256, all 256 hidden (4 chunks of 64).
// h never stored: relu + FC2 dot applied in-register per MMA tile.
#define BM   128
#define FSTR 264      // padded k-stride (bf16 elems) for fAT / w1T

// dynamic smem offsets (bytes)
#define OFF_FAT  0                        // bf16 [128][FSTR]  (pt-major, k inner)
#define OFF_W1T  (128 * FSTR * 2)         // bf16 [64][FSTR]   (n-major, k inner)
#define OFF_B1   (OFF_W1T + 64 * FSTR * 2)
#define OFF_W27  (OFF_B1 + 256 * 4)
#define ASMEM    (OFF_W27 + 256 * 4)

__global__ void __launch_bounds__(256)
approx_score_kernel(const float* __restrict__ feat, const float* __restrict__ W1,
                    const float* __restrict__ b1, const float* __restrict__ W2,
                    const float* __restrict__ b2) {
    extern __shared__ char smem[];
    __nv_bfloat16* fAT = (__nv_bfloat16*)(smem + OFF_FAT);
    __nv_bfloat16* w1T = (__nv_bfloat16*)(smem + OFF_W1T);
    float* b1s = (float*)(smem + OFF_B1);
    float* w27 = (float*)(smem + OFF_W27);

    const int tid = threadIdx.x;
    const int b = blockIdx.y;
    const int n0 = blockIdx.x * BM;
    const int lane = tid & 31;
    const int warp = tid >> 5;      // 0..7
    const int g = lane >> 2;        // 0..7
    const int tg = lane & 3;        // 0..3
    const int prow0 = warp * 16 + g;   // point row for c0/c1 (c2/c3: +8)

    // stage b1, W2[:,7]
    b1s[tid] = b1[tid];
    w27[tid] = W2[tid * OUTC + 7];
    const float b27 = b2[7];

    // stage fAT: feat[b, c, n0+pt] -> fAT[pt][c], transposed + bf16
#pragma unroll 4
    for (int it = 0; it < 32; it++) {
        int idx4 = it * 256 + tid;        // 0..8191
        int c = idx4 >> 5;                // 0..255
        int p4 = (idx4 & 31) << 2;        // 0..124
        float4 v = *(const float4*)&feat[((size_t)b * CH + c) * NPTS + n0 + p4];
        fAT[(p4 + 0) * FSTR + c] = __float2bfloat16(v.x);
        fAT[(p4 + 1) * FSTR + c] = __float2bfloat16(v.y);
        fAT[(p4 + 2) * FSTR + c] = __float2bfloat16(v.z);
        fAT[(p4 + 3) * FSTR + c] = __float2bfloat16(v.w);
    }

    float sp0 = 0.0f, sp1 = 0.0f;

#pragma unroll 1
    for (int nc = 0; nc < 4; nc++) {
        __syncthreads();   // fAT staged (nc=0) / previous w1T reads done
        // stage w1T: W1[k][nc*64+n] -> w1T[n][k]
#pragma unroll 4
        for (int it = 0; it < 16; it++) {
            int idx4 = it * 256 + tid;    // 0..4095
            int k = idx4 >> 4;            // 0..255
            int n4 = (idx4 & 15) << 2;    // 0..60
            float4 v = *(const float4*)&W1[(size_t)k * HID + nc * 64 + n4];
            w1T[(n4 + 0) * FSTR + k] = __float2bfloat16(v.x);
            w1T[(n4 + 1) * FSTR + k] = __float2bfloat16(v.y);
            w1T[(n4 + 2) * FSTR + k] = __float2bfloat16(v.z);
            w1T[(n4 + 3) * FSTR + k] = __float2bfloat16(v.w);
        }
        __syncthreads();

        float c[8][4];
#pragma unroll
        for (int nf = 0; nf < 8; nf++)
#pragma unroll
            for (int j = 0; j < 4; j++) c[nf][j] = 0.0f;

#pragma unroll 2
        for (int kt = 0; kt < 16; kt++) {
            const int k0 = kt * 16;
            unsigned a0 = *(const unsigned*)&fAT[prow0 * FSTR + k0 + 2 * tg];
            unsigned a1 = *(const unsigned*)&fAT[(prow0 + 8) * FSTR + k0 + 2 * tg];
            unsigned a2 = *(const unsigned*)&fAT[prow0 * FSTR + k0 + 8 + 2 * tg];
            unsigned a3 = *(const unsigned*)&fAT[(prow0 + 8) * FSTR + k0 + 8 + 2 * tg];
#pragma unroll
            for (int nf = 0; nf < 8; nf++) {
                unsigned bb0 = *(const unsigned*)&w1T[(nf * 8 + g) * FSTR + k0 + 2 * tg];
                unsigned bb1 = *(const unsigned*)&w1T[(nf * 8 + g) * FSTR + k0 + 8 + 2 * tg];
                asm volatile(
                    "mma.sync.aligned.m16n8k16.row.col.f32.bf16.bf16.f32 "
                    "{%0,%1,%2,%3}, {%4,%5,%6,%7}, {%8,%9}, {%0,%1,%2,%3};"
                    : "+f"(c[nf][0]), "+f"(c[nf][1]), "+f"(c[nf][2]), "+f"(c[nf][3])
                    : "r"(a0), "r"(a1), "r"(a2), "r"(a3), "r"(bb0), "r"(bb1));
            }
        }

        // relu + b1 + dot W2[:,7], in-register
#pragma unroll
        for (int nf = 0; nf < 8; nf++) {
            int col = nc * 64 + nf * 8 + 2 * tg;
            float bb0 = b1s[col], bb1 = b1s[col + 1];
            float w0 = w27[col], w1v = w27[col + 1];
            sp0 += fmaxf(c[nf][0] + bb0, 0.0f) * w0 + fmaxf(c[nf][1] + bb1, 0.0f) * w1v;
            sp1 += fmaxf(c[nf][2] + bb0, 0.0f) * w0 + fmaxf(c[nf][3] + bb1, 0.0f) * w1v;
        }
    }

    // reduce over quad (tg 0..3 hold disjoint column subsets)
    sp0 += __shfl_xor_sync(0xFFFFFFFFu, sp0, 1);
    sp0 += __shfl_xor_sync(0xFFFFFFFFu, sp0, 2);
    sp1 += __shfl_xor_sync(0xFFFFFFFFu, sp1, 1);
    sp1 += __shfl_xor_sync(0xFFFFFFFFu, sp1, 2);

    if (tg == 0) {
        int pt = n0 + warp * 16 + g;
        float s0 = sp0 + b27, s1 = sp1 + b27;
        g_score[(size_t)b * NPTS + pt] = s0;
        g_score[(size_t)b * NPTS + pt + 8] = s1;
        atomicAdd(&g_hist16[(size_t)b * 65536 + (fkey(s0) >> 16)], 1u);
        atomicAdd(&g_hist16[(size_t)b * 65536 + (fkey(s1) >> 16)], 1u);
    }
}

// ================= Phase B: threshold + band collect =========================
__global__ void thresh_kernel() {
    __shared__ unsigned int sfx[1024];
    const int b = blockIdx.x;
    const int tid = threadIdx.x;
    unsigned int* h = g_hist16 + (size_t)b * 65536;
    const int c0 = tid * 64;

    unsigned int s = 0;
#pragma unroll 8
    for (int j = 0; j < 64; j++) s += h[c0 + j];
    sfx[tid] = s;
    __syncthreads();
    for (int off = 1; off < 1024; off <<= 1) {
        unsigned int v = sfx[tid];
        unsigned int add = (tid + off < 1024) ? sfx[tid + off] : 0u;
        __syncthreads();
        sfx[tid] = v + add;
        __syncthreads();
    }
    unsigned int above = (tid < 1023) ? sfx[tid + 1] : 0u;
    if (sfx[tid] >= TOPK && above < TOPK) {
        unsigned int cum = above;
        for (int v = c0 + 63; v >= c0; v--) {
            cum += h[v];
            if (cum >= TOPK) { g_thresh[b] = v; break; }
        }
    }
    __syncthreads();
#pragma unroll 8
    for (int j = 0; j < 64; j++) h[c0 + j] = 0u;   // self-reset
}

__global__ void collect_kernel() {
    const int b = blockIdx.x;
    int t16 = g_thresh[b];
    const unsigned int v16 = (unsigned int)(t16 > BAND ? t16 - BAND : 0);
    const float* sc = g_score + (size_t)b * NPTS;
    const int base = blockIdx.y * (NPTS / 8);
    for (int i = threadIdx.x; i < NPTS / 8; i += 1024) {
        int gi = base + i;
        if ((fkey(sc[gi]) >> 16) >= v16) {
            int p = atomicAdd(&g_cnt[b], 1);
            if (p < CAP) g_candidx[(size_t)b * CAP + p] = gi;
        }
    }
}

// ================= exact rescore of candidates ===============================
// FC1: ascending-c fp32 FMA chain; FC2: 4 slices chunk-4/period-16,
// combine ((s0+s1)+s2)+s3 — bit-identical to the verified passing order.
__global__ void __launch_bounds__(256)
exact_kernel(const float* __restrict__ feat, const float* __restrict__ W1,
             const float* __restrict__ b1, const float* __restrict__ W2,
             const float* __restrict__ b2) {
    __shared__ float fcol[CH][16];
    __shared__ float hs[HID][16];
    __shared__ float w2s7[256];
    __shared__ float ps[64];
    __shared__ int nidx[16];

    const int tid = threadIdx.x;
    const int b = blockIdx.x;
    const int cnt0 = g_cnt[b];
    const int cnt = cnt0 < CAP ? cnt0 : CAP;
    const float b27 = b2[7];

    w2s7[tid] = W2[tid * OUTC + 7];

    for (int base = blockIdx.y * 16; base < cnt; base += gridDim.y * 16) {
        const int m = (cnt - base) < 16 ? (cnt - base) : 16;
        __syncthreads();
        if (tid < 16)
            nidx[tid] = g_candidx[(size_t)b * CAP + base + (tid < m ? tid : 0)];
        __syncthreads();

#pragma unroll
        for (int p = 0; p < 16; p++)
            fcol[tid][p] = feat[((size_t)b * CH + tid) * NPTS + nidx[p]];
        __syncthreads();

        float acc[16];
#pragma unroll
        for (int p = 0; p < 16; p++) acc[p] = 0.0f;
#pragma unroll 4
        for (int c = 0; c < CH; c++) {
            float w = W1[(size_t)c * HID + tid];
#pragma unroll
            for (int p = 0; p < 16; p++) acc[p] = fmaf(fcol[c][p], w, acc[p]);
        }
        float b1v = b1[tid];
#pragma unroll
        for (int p = 0; p < 16; p++) hs[tid][p] = fmaxf(acc[p] + b1v, 0.0f);
        __syncthreads();

        if (tid < 64) {
            const int pt = tid >> 2, z = tid & 3;
            float a = 0.0f;
#pragma unroll
            for (int i = 0; i < 16; i++) {
                int kb = 16 * i + 4 * z;
#pragma unroll
                for (int kk = 0; kk < 4; kk++)
                    a = fmaf(hs[kb + kk][pt], w2s7[kb + kk], a);
            }
            ps[pt * 4 + z] = a;
        }
        __syncthreads();

        if (tid < m) {
            float sc = ((ps[tid * 4 + 0] + ps[tid * 4 + 1]) + ps[tid * 4 + 2]) + ps[tid * 4 + 3];
            sc += b27;
            g_cand[(size_t)b * CAP + base + tid] =
                ((unsigned long long)fkey(sc) << 32) |
                (unsigned long long)(0xFFFFFFFFu - (unsigned int)nidx[tid]);
        }
    }
}

// ================= sort candidates, emit exact top-512 =======================
__global__ void sort_kernel() {
    extern __shared__ unsigned long long cand[];
    __shared__ int s_m;
    const int b = blockIdx.x;
    const int tid = threadIdx.x;

    const int M0 = g_cnt[b];
    const int M = M0 < CAP ? M0 : CAP;
    if (tid == 0) {
        int m = 1024;
        while (m < M) m <<= 1;
        s_m = m;
    }
    __syncthreads();
    const int m = s_m;

    for (int i = tid; i < m; i += 1024)
        cand[i] = (i < M) ? g_cand[(size_t)b * CAP + i] : 0ULL;
    __syncthreads();

    for (unsigned int k = 2; k <= (unsigned int)m; k <<= 1) {
        for (unsigned int j = k >> 1; j > 0; j >>= 1) {
            for (unsigned int i = tid; i < (unsigned int)m; i += 1024) {
                unsigned int ixj = i ^ j;
                if (ixj > i) {
                    unsigned long long a = cand[i], c2 = cand[ixj];
                    bool up = ((i & k) == 0);
                    if ((a > c2) == up) { cand[i] = c2; cand[ixj] = a; }
                }
            }
            __syncthreads();
        }
    }
    if (tid < TOPK) {
        unsigned long long e = cand[m - 1 - tid];
        g_topk_idx[b * TOPK + tid] =
            (int)(0xFFFFFFFFu - (unsigned int)(e & 0xFFFFFFFFULL));
    }
    if (tid == 0) g_cnt[b] = 0;   // self-reset
}

// ================= Phase C: exact full rows at selected points ===============
#define GP 16
__global__ void __launch_bounds__(256)
gather_kernel(const float* __restrict__ feat, const float* __restrict__ W1,
              const float* __restrict__ b1, const float* __restrict__ W2,
              const float* __restrict__ b2, float* __restrict__ out) {
    __shared__ float fcol[CH][GP];
    __shared__ float hs[HID][GP];
    __shared__ float w2s[HID * OUTC];
    __shared__ int nidx[GP];

    const int tid = threadIdx.x;
    const int b = blockIdx.x >> 5;
    const int r0 = (blockIdx.x & 31) * GP;

    if (tid < GP) nidx[tid] = g_topk_idx[b * TOPK + r0 + tid];
    for (int i = tid; i < HID * OUTC; i += 256) w2s[i] = W2[i];
    __syncthreads();

#pragma unroll
    for (int p = 0; p < GP; p++)
        fcol[tid][p] = feat[((size_t)b * CH + tid) * NPTS + nidx[p]];
    __syncthreads();

    float acc[GP];
#pragma unroll
    for (int p = 0; p < GP; p++) acc[p] = 0.0f;
#pragma unroll 4
    for (int c = 0; c < CH; c++) {
        float w = W1[(size_t)c * HID + tid];
#pragma unroll
        for (int p = 0; p < GP; p++) acc[p] = fmaf(fcol[c][p], w, acc[p]);
    }
    float b1v = b1[tid];
#pragma unroll
    for (int p = 0; p < GP; p++) hs[tid][p] = fmaxf(acc[p] + b1v, 0.0f);
    __syncthreads();

    if (tid < GP * OUTC) {
        int p = tid >> 3, o = tid & 7;
        float a = 0.0f;
#pragma unroll 16
        for (int hh = 0; hh < HID; hh++)
            a = fmaf(hs[hh][p], w2s[hh * OUTC + o], a);
        out[((size_t)(b * TOPK + r0 + p)) * OUTC + o] = a + b2[o];
    }
}

// ---------------- launch ----------------
extern "C" void kernel_launch(void* const* d_in, const int* in_sizes, int n_in,
                              void* d_out, int out_size) {
    // inputs: 0 points(unused), 1 features, 2 W1, 3 b1, 4 W2, 5 b2, 6 topk
    const float* feat = (const float*)d_in[1];
    const float* W1 = (const float*)d_in[2];
    const float* b1 = (const float*)d_in[3];
    const float* W2 = (const float*)d_in[4];
    const float* b2 = (const float*)d_in[5];
    float* out = (float*)d_out;

    cudaFuncSetAttribute(approx_score_kernel,
                         cudaFuncAttributeMaxDynamicSharedMemorySize, ASMEM);
    cudaFuncSetAttribute(sort_kernel, cudaFuncAttributeMaxDynamicSharedMemorySize,
                         CAP * (int)sizeof(unsigned long long));

    dim3 gA(NPTS / BM, BATCH);
    approx_score_kernel<<<gA, 256, ASMEM>>>(feat, W1, b1, W2, b2);
    thresh_kernel<<<BATCH, 1024>>>();
    collect_kernel<<<dim3(BATCH, 8), 1024>>>();
    exact_kernel<<<dim3(BATCH, 64), 256>>>(feat, W1, b1, W2, b2);
    sort_kernel<<<BATCH, 1024, CAP * sizeof(unsigned long long)>>>();
    gather_kernel<<<BATCH * (TOPK / GP), 256>>>(feat, W1, b1, W2, b2, out);
}

// round 9
// speedup vs baseline: 3.8287x; 2.1702x over previous
#include <cuda_runtime.h>
#include <cuda_bf16.h>

// Problem constants (fixed by the dataset)
#define BATCH 8
#define CH    256
#define NPTS  65536
#define HID   256
#define OUTC  8
#define TOPK  512

#define CAP   8192
#define BAND  16       // 16-bit buckets below approx threshold to keep (~7x max bf16 err)

// Scratch (no cudaMalloc). Zero-init at load; consumers self-reset for replay.
__device__ float g_score[BATCH * NPTS];
__device__ int   g_topk_idx[BATCH * TOPK];
__device__ unsigned int g_hist16[BATCH * 65536];
__device__ int g_candidx[BATCH * CAP];
__device__ unsigned long long g_cand[BATCH * CAP];
__device__ int g_cnt[BATCH];
__device__ int g_thresh[BATCH];
__device__ __nv_bfloat16 g_w1bf[CH * HID];   // pre-converted W1 (recomputed each replay)

__device__ __forceinline__ unsigned int fkey(float f) {
    unsigned int u = __float_as_uint(f);
    return (u & 0x80000000u) ? ~u : (u | 0x80000000u);
}

// ---------------- cp.async helpers ----------------
__device__ __forceinline__ void cp16(void* dst_smem, const void* src) {
    unsigned s = (unsigned)__cvta_generic_to_shared(dst_smem);
    asm volatile("cp.async.cg.shared.global [%0], [%1], 16;" :: "r"(s), "l"(src));
}
__device__ __forceinline__ void cp_commit() { asm volatile("cp.async.commit_group;"); }
__device__ __forceinline__ void cp_wait1() { asm volatile("cp.async.wait_group 1;"); }
__device__ __forceinline__ void cp_wait0() { asm volatile("cp.async.wait_group 0;"); }

#define LDSM4T(r0, r1, r2, r3, addr)                                          \
    asm volatile("ldmatrix.sync.aligned.m8n8.x4.trans.shared.b16 "            \
                 "{%0,%1,%2,%3}, [%4];"                                       \
                 : "=r"(r0), "=r"(r1), "=r"(r2), "=r"(r3) : "r"(addr))

// ================= W1 -> bf16 pre-convert =====================================
__global__ void w1bf_kernel(const float* __restrict__ W1) {
    int i = blockIdx.x * 1024 + threadIdx.x;
    g_w1bf[i] = __float2bfloat16(W1[i]);
}

// ================= Phase A: approx scores via bf16 MMA + ldmatrix ============
// Block: 256 points, full K=256, HID in 4 chunks of 64 (relu+dot folded in-reg).
#define BM      256
#define ROWB_F  264                   // fB row stride (bf16 elems): 256 pts + 8 pad
#define ROWB_W  72                    // w1S row stride: 64 n + 8 pad
#define FB_ELEMS  (256 * ROWB_F)      // 67584
#define W1S_ELEMS (256 * ROWB_W)      // 18432
#define ASMEM   ((FB_ELEMS + 2 * W1S_ELEMS) * 2)   // 208896 bytes

__global__ void __launch_bounds__(256)
approx_score_kernel(const float* __restrict__ feat, const float* __restrict__ b1,
                    const float* __restrict__ W2, const float* __restrict__ b2) {
    extern __shared__ __nv_bfloat16 smem[];
    __nv_bfloat16* fB = smem;                       // [256 k][ROWB_F]  natural [c][pt]
    __nv_bfloat16* w1s = smem + FB_ELEMS;           // 2 x [256 k][ROWB_W] natural [k][n]
    __shared__ float b1s[256];
    __shared__ float w27[256];

    const int tid = threadIdx.x;
    const int b = blockIdx.y;
    const int n0 = blockIdx.x * BM;
    const int lane = tid & 31;
    const int warp = tid >> 5;          // 0..7 -> 32 points each
    const int g = lane >> 2;
    const int tg = lane & 3;
    const int P0 = warp * 32;

    // ldmatrix lane address components
    const int aK = (lane & 7) + ((lane & 16) >> 1);
    const int aP = lane & 8;
    const int bK = lane & 15;
    const int bN = (lane & 16) >> 1;

    const unsigned fB_u = (unsigned)__cvta_generic_to_shared(fB);
    const unsigned w1_u = (unsigned)__cvta_generic_to_shared(w1s);

    b1s[tid] = b1[tid];
    w27[tid] = W2[tid * OUTC + 7];
    const float b27 = b2[7];

    // issue W1 chunk nc into buffer buf (cp.async from pre-converted bf16)
    auto issue = [&](int nc, int buf) {
#pragma unroll
        for (int j = 0; j < 8; j++) {
            int idx = j * 256 + tid;        // 0..2047
            int k = idx >> 3;
            int seg = idx & 7;
            cp16(&w1s[buf * W1S_ELEMS + k * ROWB_W + seg * 8],
                 &g_w1bf[k * HID + nc * 64 + seg * 8]);
        }
        cp_commit();
    };

    issue(0, 0);
    issue(1, 1);

    // stage fB: feat [c][n0..n0+255] -> bf16 natural layout (coalesced, conflict-free)
    const float* fbase = feat + (size_t)b * CH * NPTS + n0;
#pragma unroll 8
    for (int it = 0; it < 64; it++) {
        int idx4 = it * 256 + tid;          // 0..16383
        int c = idx4 >> 6;
        int p4 = (idx4 & 63) << 2;
        float4 v = *(const float4*)&fbase[(size_t)c * NPTS + p4];
        __nv_bfloat162 lo = __floats2bfloat162_rn(v.x, v.y);
        __nv_bfloat162 hi = __floats2bfloat162_rn(v.z, v.w);
        *reinterpret_cast<__nv_bfloat162*>(&fB[c * ROWB_F + p4]) = lo;
        *reinterpret_cast<__nv_bfloat162*>(&fB[c * ROWB_F + p4 + 2]) = hi;
    }

    float sp[4] = {0.0f, 0.0f, 0.0f, 0.0f};

#pragma unroll 1
    for (int nc = 0; nc < 4; nc++) {
        if (nc < 3) cp_wait1(); else cp_wait0();
        __syncthreads();    // w1s[nc&1] staged; fB staged (nc=0); prev buf free

        const unsigned wb = w1_u + (unsigned)((nc & 1) * W1S_ELEMS * 2);

        float c[2][8][4];
#pragma unroll
        for (int mi = 0; mi < 2; mi++)
#pragma unroll
            for (int nt = 0; nt < 8; nt++)
#pragma unroll
                for (int j = 0; j < 4; j++) c[mi][nt][j] = 0.0f;

#pragma unroll 4
        for (int kt = 0; kt < 16; kt++) {
            const int k0 = kt * 16;
            unsigned a[2][4];
#pragma unroll
            for (int mi = 0; mi < 2; mi++)
                LDSM4T(a[mi][0], a[mi][1], a[mi][2], a[mi][3],
                       fB_u + (unsigned)(((k0 + aK) * ROWB_F + P0 + mi * 16 + aP) * 2));
            unsigned bq[4][4];
#pragma unroll
            for (int bi = 0; bi < 4; bi++)
                LDSM4T(bq[bi][0], bq[bi][1], bq[bi][2], bq[bi][3],
                       wb + (unsigned)(((k0 + bK) * ROWB_W + bi * 16 + bN) * 2));
#pragma unroll
            for (int mi = 0; mi < 2; mi++)
#pragma unroll
                for (int nt = 0; nt < 8; nt++) {
                    const int bi = nt >> 1, pr = (nt & 1) * 2;
                    asm volatile(
                        "mma.sync.aligned.m16n8k16.row.col.f32.bf16.bf16.f32 "
                        "{%0,%1,%2,%3}, {%4,%5,%6,%7}, {%8,%9}, {%0,%1,%2,%3};"
                        : "+f"(c[mi][nt][0]), "+f"(c[mi][nt][1]),
                          "+f"(c[mi][nt][2]), "+f"(c[mi][nt][3])
                        : "r"(a[mi][0]), "r"(a[mi][1]), "r"(a[mi][2]), "r"(a[mi][3]),
                          "r"(bq[bi][pr]), "r"(bq[bi][pr + 1]));
                }
        }

        // relu + b1 + dot W2[:,7] in-register
#pragma unroll
        for (int mi = 0; mi < 2; mi++)
#pragma unroll
            for (int nt = 0; nt < 8; nt++) {
                int col = nc * 64 + nt * 8 + 2 * tg;
                float bb0 = b1s[col], bb1 = b1s[col + 1];
                float w0 = w27[col], w1v = w27[col + 1];
                sp[2 * mi + 0] += fmaxf(c[mi][nt][0] + bb0, 0.0f) * w0 +
                                  fmaxf(c[mi][nt][1] + bb1, 0.0f) * w1v;
                sp[2 * mi + 1] += fmaxf(c[mi][nt][2] + bb0, 0.0f) * w0 +
                                  fmaxf(c[mi][nt][3] + bb1, 0.0f) * w1v;
            }

        __syncthreads();    // all warps done reading w1s[nc&1]
        if (nc + 2 < 4) issue(nc + 2, nc & 1);
    }

    // quad-reduce over tg (disjoint hid columns)
#pragma unroll
    for (int j = 0; j < 4; j++) {
        sp[j] += __shfl_xor_sync(0xFFFFFFFFu, sp[j], 1);
        sp[j] += __shfl_xor_sync(0xFFFFFFFFu, sp[j], 2);
    }

    if (tg == 0) {
        const int pts[4] = { P0 + g, P0 + g + 8, P0 + 16 + g, P0 + 24 + g };
#pragma unroll
        for (int j = 0; j < 4; j++) {
            float s = sp[j] + b27;
            g_score[(size_t)b * NPTS + n0 + pts[j]] = s;
            atomicAdd(&g_hist16[(size_t)b * 65536 + (fkey(s) >> 16)], 1u);
        }
    }
}

// ================= Phase B: threshold + band collect =========================
__global__ void thresh_kernel() {
    __shared__ unsigned int sfx[1024];
    const int b = blockIdx.x;
    const int tid = threadIdx.x;
    unsigned int* h = g_hist16 + (size_t)b * 65536;
    const int c0 = tid * 64;

    unsigned int s = 0;
#pragma unroll 8
    for (int j = 0; j < 64; j++) s += h[c0 + j];
    sfx[tid] = s;
    __syncthreads();
    for (int off = 1; off < 1024; off <<= 1) {
        unsigned int v = sfx[tid];
        unsigned int add = (tid + off < 1024) ? sfx[tid + off] : 0u;
        __syncthreads();
        sfx[tid] = v + add;
        __syncthreads();
    }
    unsigned int above = (tid < 1023) ? sfx[tid + 1] : 0u;
    if (sfx[tid] >= TOPK && above < TOPK) {
        unsigned int cum = above;
        for (int v = c0 + 63; v >= c0; v--) {
            cum += h[v];
            if (cum >= TOPK) { g_thresh[b] = v; break; }
        }
    }
    __syncthreads();
#pragma unroll 8
    for (int j = 0; j < 64; j++) h[c0 + j] = 0u;   // self-reset
}

__global__ void collect_kernel() {
    const int b = blockIdx.x;
    int t16 = g_thresh[b];
    const unsigned int v16 = (unsigned int)(t16 > BAND ? t16 - BAND : 0);
    const float* sc = g_score + (size_t)b * NPTS;
    const int base = blockIdx.y * (NPTS / 8);
    for (int i = threadIdx.x; i < NPTS / 8; i += 1024) {
        int gi = base + i;
        if ((fkey(sc[gi]) >> 16) >= v16) {
            int p = atomicAdd(&g_cnt[b], 1);
            if (p < CAP) g_candidx[(size_t)b * CAP + p] = gi;
        }
    }
}

// ================= exact rescore (bit-identical chains) ======================
__global__ void __launch_bounds__(256)
exact_kernel(const float* __restrict__ feat, const float* __restrict__ W1,
             const float* __restrict__ b1, const float* __restrict__ W2,
             const float* __restrict__ b2) {
    __shared__ float fcol[CH][16];
    __shared__ float hs[HID][16];
    __shared__ float w2s7[256];
    __shared__ float ps[64];
    __shared__ int nidx[16];

    const int tid = threadIdx.x;
    const int b = blockIdx.x;
    const int cnt0 = g_cnt[b];
    const int cnt = cnt0 < CAP ? cnt0 : CAP;
    const float b27 = b2[7];

    w2s7[tid] = W2[tid * OUTC + 7];

    for (int base = blockIdx.y * 16; base < cnt; base += gridDim.y * 16) {
        const int m = (cnt - base) < 16 ? (cnt - base) : 16;
        __syncthreads();
        if (tid < 16)
            nidx[tid] = g_candidx[(size_t)b * CAP + base + (tid < m ? tid : 0)];
        __syncthreads();

#pragma unroll
        for (int p = 0; p < 16; p++)
            fcol[tid][p] = feat[((size_t)b * CH + tid) * NPTS + nidx[p]];
        __syncthreads();

        float acc[16];
#pragma unroll
        for (int p = 0; p < 16; p++) acc[p] = 0.0f;
#pragma unroll 4
        for (int c = 0; c < CH; c++) {
            float w = W1[(size_t)c * HID + tid];
#pragma unroll
            for (int p = 0; p < 16; p++) acc[p] = fmaf(fcol[c][p], w, acc[p]);
        }
        float b1v = b1[tid];
#pragma unroll
        for (int p = 0; p < 16; p++) hs[tid][p] = fmaxf(acc[p] + b1v, 0.0f);
        __syncthreads();

        if (tid < 64) {
            const int pt = tid >> 2, z = tid & 3;
            float a = 0.0f;
#pragma unroll
            for (int i = 0; i < 16; i++) {
                int kb = 16 * i + 4 * z;
#pragma unroll
                for (int kk = 0; kk < 4; kk++)
                    a = fmaf(hs[kb + kk][pt], w2s7[kb + kk], a);
            }
            ps[pt * 4 + z] = a;
        }
        __syncthreads();

        if (tid < m) {
            float sc = ((ps[tid * 4 + 0] + ps[tid * 4 + 1]) + ps[tid * 4 + 2]) + ps[tid * 4 + 3];
            sc += b27;
            g_cand[(size_t)b * CAP + base + tid] =
                ((unsigned long long)fkey(sc) << 32) |
                (unsigned long long)(0xFFFFFFFFu - (unsigned int)nidx[tid]);
        }
    }
}

// ================= sort candidates, emit exact top-512 =======================
__global__ void sort_kernel() {
    extern __shared__ unsigned long long cand[];
    __shared__ int s_m;
    const int b = blockIdx.x;
    const int tid = threadIdx.x;

    const int M0 = g_cnt[b];
    const int M = M0 < CAP ? M0 : CAP;
    if (tid == 0) {
        int m = 1024;
        while (m < M) m <<= 1;
        s_m = m;
    }
    __syncthreads();
    const int m = s_m;

    for (int i = tid; i < m; i += 1024)
        cand[i] = (i < M) ? g_cand[(size_t)b * CAP + i] : 0ULL;
    __syncthreads();

    for (unsigned int k = 2; k <= (unsigned int)m; k <<= 1) {
        for (unsigned int j = k >> 1; j > 0; j >>= 1) {
            for (unsigned int i = tid; i < (unsigned int)m; i += 1024) {
                unsigned int ixj = i ^ j;
                if (ixj > i) {
                    unsigned long long a = cand[i], c2 = cand[ixj];
                    bool up = ((i & k) == 0);
                    if ((a > c2) == up) { cand[i] = c2; cand[ixj] = a; }
                }
            }
            __syncthreads();
        }
    }
    if (tid < TOPK) {
        unsigned long long e = cand[m - 1 - tid];
        g_topk_idx[b * TOPK + tid] =
            (int)(0xFFFFFFFFu - (unsigned int)(e & 0xFFFFFFFFULL));
    }
    if (tid == 0) g_cnt[b] = 0;   // self-reset
}

// ================= Phase C: exact full rows ==================================
#define GP 16
__global__ void __launch_bounds__(256)
gather_kernel(const float* __restrict__ feat, const float* __restrict__ W1,
              const float* __restrict__ b1, const float* __restrict__ W2,
              const float* __restrict__ b2, float* __restrict__ out) {
    __shared__ float fcol[CH][GP];
    __shared__ float hs[HID][GP];
    __shared__ float w2s[HID * OUTC];
    __shared__ int nidx[GP];

    const int tid = threadIdx.x;
    const int b = blockIdx.x >> 5;
    const int r0 = (blockIdx.x & 31) * GP;

    if (tid < GP) nidx[tid] = g_topk_idx[b * TOPK + r0 + tid];
    for (int i = tid; i < HID * OUTC; i += 256) w2s[i] = W2[i];
    __syncthreads();

#pragma unroll
    for (int p = 0; p < GP; p++)
        fcol[tid][p] = feat[((size_t)b * CH + tid) * NPTS + nidx[p]];
    __syncthreads();

    float acc[GP];
#pragma unroll
    for (int p = 0; p < GP; p++) acc[p] = 0.0f;
#pragma unroll 4
    for (int c = 0; c < CH; c++) {
        float w = W1[(size_t)c * HID + tid];
#pragma unroll
        for (int p = 0; p < GP; p++) acc[p] = fmaf(fcol[c][p], w, acc[p]);
    }
    float b1v = b1[tid];
#pragma unroll
    for (int p = 0; p < GP; p++) hs[tid][p] = fmaxf(acc[p] + b1v, 0.0f);
    __syncthreads();

    if (tid < GP * OUTC) {
        int p = tid >> 3, o = tid & 7;
        float a = 0.0f;
#pragma unroll 16
        for (int hh = 0; hh < HID; hh++)
            a = fmaf(hs[hh][p], w2s[hh * OUTC + o], a);
        out[((size_t)(b * TOPK + r0 + p)) * OUTC + o] = a + b2[o];
    }
}

// ---------------- launch ----------------
extern "C" void kernel_launch(void* const* d_in, const int* in_sizes, int n_in,
                              void* d_out, int out_size) {
    // inputs: 0 points(unused), 1 features, 2 W1, 3 b1, 4 W2, 5 b2, 6 topk
    const float* feat = (const float*)d_in[1];
    const float* W1 = (const float*)d_in[2];
    const float* b1 = (const float*)d_in[3];
    const float* W2 = (const float*)d_in[4];
    const float* b2 = (const float*)d_in[5];
    float* out = (float*)d_out;

    cudaFuncSetAttribute(approx_score_kernel,
                         cudaFuncAttributeMaxDynamicSharedMemorySize, ASMEM);
    cudaFuncSetAttribute(sort_kernel, cudaFuncAttributeMaxDynamicSharedMemorySize,
                         CAP * (int)sizeof(unsigned long long));

    w1bf_kernel<<<64, 1024>>>(W1);
    approx_score_kernel<<<dim3(NPTS / BM, BATCH), 256, ASMEM>>>(feat, b1, W2, b2);
    thresh_kernel<<<BATCH, 1024>>>();
    collect_kernel<<<dim3(BATCH, 8), 1024>>>();
    exact_kernel<<<dim3(BATCH, 64), 256>>>(feat, W1, b1, W2, b2);
    sort_kernel<<<BATCH, 1024, CAP * sizeof(unsigned long long)>>>();
    gather_kernel<<<BATCH * (TOPK / GP), 256>>>(feat, W1, b1, W2, b2, out);
}